// round 15
// baseline (speedup 1.0000x reference)
#include <cuda_runtime.h>
#include <cuda_fp16.h>
#include <math.h>
#include <float.h>
#include <stdint.h>

#define DIM 2048
#define QKVD 3072
#define NHEADS 16
#define NKV 4
#define HD 128
#define BATCH 2
#define SEQ 2048
#define BT (BATCH*SEQ)     // 4096
#define KVDIM 512

// Scratch (__device__ globals per allocation-free rule)
__device__ __align__(16) __half g_qkvh[(size_t)BT*QKVD];   // qkv (fp16)
__device__ __align__(16) __half g_xh[(size_t)BT*DIM];
__device__ __align__(16) __half g_wqkvh[(size_t)QKVD*DIM];
__device__ __align__(16) __half g_wph[(size_t)DIM*DIM];
__device__ __align__(16) __half g_yh[(size_t)BT*DIM];      // attention output (fp16)
__device__ __align__(16) float2 g_tab[SEQ*64];

// ---------------------------------------------------------------------------
// helpers
// ---------------------------------------------------------------------------
__device__ __forceinline__ uint32_t pack2(float a, float b) {
    __half2 h = __floats2half2_rn(a, b);
    return *(uint32_t*)&h;
}

__device__ __forceinline__ void mma_f16(float4& c, const uint32_t* a,
                                        uint32_t b0, uint32_t b1) {
    asm volatile(
        "mma.sync.aligned.m16n8k16.row.col.f32.f16.f16.f32 "
        "{%0,%1,%2,%3}, {%4,%5,%6,%7}, {%8,%9}, {%0,%1,%2,%3};"
        : "+f"(c.x), "+f"(c.y), "+f"(c.z), "+f"(c.w)
        : "r"(a[0]), "r"(a[1]), "r"(a[2]), "r"(a[3]), "r"(b0), "r"(b1));
}

__device__ __forceinline__ void cp_async16(uint32_t s, const void* g) {
    asm volatile("cp.async.cg.shared.global [%0], [%1], 16;" :: "r"(s), "l"(g));
}
__device__ __forceinline__ void cp_commit() {
    asm volatile("cp.async.commit_group;");
}
template<int N> __device__ __forceinline__ void cp_wait() {
    asm volatile("cp.async.wait_group %0;" :: "n"(N));
}

__device__ __forceinline__ uint32_t sm_u32(const void* p) {
    return (uint32_t)__cvta_generic_to_shared(p);
}

__device__ __forceinline__ void ldsm_x4(uint32_t* r, uint32_t addr) {
    asm volatile("ldmatrix.sync.aligned.m8n8.x4.shared.b16 {%0,%1,%2,%3}, [%4];"
                 : "=r"(r[0]), "=r"(r[1]), "=r"(r[2]), "=r"(r[3]) : "r"(addr));
}
__device__ __forceinline__ void ldsm_x4t(uint32_t* r, uint32_t addr) {
    asm volatile("ldmatrix.sync.aligned.m8n8.x4.trans.shared.b16 {%0,%1,%2,%3}, [%4];"
                 : "=r"(r[0]), "=r"(r[1]), "=r"(r[2]), "=r"(r[3]) : "r"(addr));
}

// swizzle a 16B-chunk index within a row (toggles low 3 bits only)
__device__ __forceinline__ uint32_t swz(uint32_t c, uint32_t r) {
    return (c & ~7u) | ((c ^ (r & 7u)) & 7u);
}

// ---------------------------------------------------------------------------
// prep_all: fp32 -> fp16 conversion of x + weights, plus RoPE table.
// ---------------------------------------------------------------------------
#define BLH_X  4096
#define BLH_WQ 2048
#define BLH_WK 512
#define BLH_WV 512
#define BLH_WP 2048
#define BLH_TB 512

__global__ __launch_bounds__(256) void prep_all(const float* __restrict__ x,
                                                const float* __restrict__ Wq,
                                                const float* __restrict__ Wk,
                                                const float* __restrict__ Wv,
                                                const float* __restrict__ Wp)
{
    int blk = blockIdx.x;
    const float* src;
    __half* dst;
    if (blk < BLH_X)                  { src = x;  dst = g_xh; }
    else if ((blk -= BLH_X) < BLH_WQ) { src = Wq; dst = g_wqkvh; }
    else if ((blk -= BLH_WQ) < BLH_WK){ src = Wk; dst = g_wqkvh + (size_t)2048 * DIM; }
    else if ((blk -= BLH_WK) < BLH_WV){ src = Wv; dst = g_wqkvh + (size_t)2560 * DIM; }
    else if ((blk -= BLH_WV) < BLH_WP){ src = Wp; dst = g_wph; }
    else {
        blk -= BLH_WP;   // rope table
        int idx = blk * 256 + threadIdx.x;
        int t = idx >> 6, j = idx & 63;
        float inv_freq = expf(-(float)j * (9.210340371976184f / 64.0f));
        float ang = (float)t * inv_freq;
        float sn, cs;
        sincosf(ang, &sn, &cs);
        g_tab[idx] = make_float2(cs, sn);
        return;
    }
    int i = (blk * 256 + threadIdx.x) * 8;
    float4 v0 = *(const float4*)(src + i);
    float4 v1 = *(const float4*)(src + i + 4);
    uint4 o;
    o.x = pack2(v0.x, v0.y);
    o.y = pack2(v0.z, v0.w);
    o.z = pack2(v1.x, v1.y);
    o.w = pack2(v1.z, v1.w);
    *(uint4*)(dst + i) = o;
}

// ---------------------------------------------------------------------------
// warp-per-unit norm/rope, in-place on fp16 g_qkvh, half2-vectorized.
// ---------------------------------------------------------------------------
__global__ __launch_bounds__(256) void norm_rope4(const float* __restrict__ q_gain)
{
    int u = blockIdx.x * 8 + (threadIdx.x >> 5);
    int lane = threadIdx.x & 31;
    int row = u / 20;
    int h = u - row * 20;

    __half2* p2;
    float g;
    if (h < NHEADS) {
        p2 = (__half2*)(g_qkvh + (size_t)row * QKVD + h * HD);
        g = q_gain[h] * 0.08838834764831845f * 1.4426950408889634f;
    } else {
        p2 = (__half2*)(g_qkvh + (size_t)row * QKVD + 2048 + (h - NHEADS) * HD);
        g = 1.0f;
    }

    __half2 ha = p2[lane];
    __half2 hb = p2[lane + 32];
    float2 a = __half22float2(ha);
    float2 b = __half22float2(hb);

    float ss = a.x * a.x + a.y * a.y + b.x * b.x + b.y * b.y;
#pragma unroll
    for (int o = 16; o; o >>= 1) ss += __shfl_xor_sync(0xffffffffu, ss, o);
    float r = rsqrtf(ss * (1.0f / 128.0f) + 1.1920928955078125e-07f);
    a.x *= r; a.y *= r; b.x *= r; b.y *= r;

    int t = row & (SEQ - 1);
    float2 cs0 = g_tab[t * 64 + 2 * lane];
    float2 cs1 = g_tab[t * 64 + 2 * lane + 1];

    float y1x = (a.x * cs0.x + b.x * cs0.y) * g;
    float y2x = (-a.x * cs0.y + b.x * cs0.x) * g;
    float y1y = (a.y * cs1.x + b.y * cs1.y) * g;
    float y2y = (-a.y * cs1.y + b.y * cs1.x) * g;

    p2[lane]      = __floats2half2_rn(y1x, y1y);
    p2[lane + 32] = __floats2half2_rn(y2x, y2y);
}

// ---------------------------------------------------------------------------
// fp16 HMMA GEMM: C[M,N] = A[M,K](f16) @ B[N,K](f16)^T, OutT in {float,__half}
// CTA tile 128x128x64, 128 threads (4 warps 2x2, warp tile 64x64).
// 2-stage pipeline (32KB/stage -> 64KB smem), reg-capped for 3 CTAs/SM
// (12 warps/SM: hides barrier + load latency; proj grid = 1.15 waves).
// ---------------------------------------------------------------------------
#define STAGE_B 32768

template<typename OutT>
__global__ __launch_bounds__(128, 3) void gemm_h(const __half* __restrict__ A,
                                                 const __half* __restrict__ B,
                                                 OutT* __restrict__ C,
                                                 int N, int K)
{
    extern __shared__ __align__(16) char smem[];
    const int tid = threadIdx.x;
    const int wid = tid >> 5, lane = tid & 31;
    const int wm = wid >> 1, wn = wid & 1;
    const int gid = lane >> 2, tig = lane & 3;
    const int row0 = blockIdx.y * 128, col0 = blockIdx.x * 128;
    uint32_t sbase = sm_u32(smem);

    float4 acc[4][8];
#pragma unroll
    for (int i = 0; i < 4; i++)
#pragma unroll
        for (int j = 0; j < 8; j++) acc[i][j] = make_float4(0.f, 0.f, 0.f, 0.f);

    auto ld_tile = [&](int t, int s) {
        int k0 = t << 6;
        uint32_t sa = sbase + s * STAGE_B;
        uint32_t sb = sa + 16384;
        const __half* ga = A + (size_t)row0 * K + k0;
        const __half* gb = B + (size_t)col0 * K + k0;
#pragma unroll
        for (int i = 0; i < 8; i++) {
            int id = tid + i * 128;
            int r = id >> 3, c = id & 7;
            uint32_t off = (uint32_t)(r * 128 + ((c ^ (r & 7)) << 4));
            cp_async16(sa + off, ga + (size_t)r * K + c * 8);
            cp_async16(sb + off, gb + (size_t)r * K + c * 8);
        }
        cp_commit();
    };

    const int lx = lane & 7;
    const int l15 = lane & 15;
    const int lb16 = (lane >> 4) & 1;
    const int lb8 = (lane >> 3) & 1;

    const int nT = K >> 6;
    ld_tile(0, 0);
    ld_tile(1, 1);

    for (int t = 0; t < nT; t++) {
        if (t + 1 < nT) cp_wait<1>(); else cp_wait<0>();
        __syncthreads();

        uint32_t sa = sbase + (t & 1) * STAGE_B;
        uint32_t sb = sa + 16384;
#pragma unroll
        for (int ks = 0; ks < 4; ks++) {
            uint32_t a[4][4], b[4][4];
#pragma unroll
            for (int mt = 0; mt < 4; mt++) {
                int row = wm * 64 + mt * 16 + l15;
                uint32_t chunk = (uint32_t)(2 * ks + lb16);
                ldsm_x4(a[mt], sa + (uint32_t)(row * 128)
                               + (((chunk ^ (row & 7)) & 7) << 4));
            }
#pragma unroll
            for (int nb = 0; nb < 4; nb++) {
                int row = wn * 64 + nb * 16 + lb16 * 8 + lx;
                uint32_t chunk = (uint32_t)(2 * ks + lb8);
                ldsm_x4(b[nb], sb + (uint32_t)(row * 128)
                               + (((chunk ^ (row & 7)) & 7) << 4));
            }
#pragma unroll
            for (int mt = 0; mt < 4; mt++)
#pragma unroll
                for (int nb = 0; nb < 4; nb++) {
                    mma_f16(acc[mt][2*nb],     a[mt], b[nb][0], b[nb][1]);
                    mma_f16(acc[mt][2*nb + 1], a[mt], b[nb][2], b[nb][3]);
                }
        }
        __syncthreads();         // all warps done reading this stage
        if (t + 2 < nT) ld_tile(t + 2, t & 1);
    }

#pragma unroll
    for (int mt = 0; mt < 4; mt++) {
        int r = row0 + wm * 64 + mt * 16 + gid;
#pragma unroll
        for (int nt = 0; nt < 8; nt++) {
            int c = col0 + wn * 64 + nt * 8 + tig * 2;
            if (sizeof(OutT) == 2) {
                *(uint32_t*)&C[(size_t)r * N + c] = pack2(acc[mt][nt].x, acc[mt][nt].y);
                *(uint32_t*)&C[(size_t)(r + 8) * N + c] = pack2(acc[mt][nt].z, acc[mt][nt].w);
            } else {
                *(float2*)&C[(size_t)r * N + c] =
                    make_float2(acc[mt][nt].x, acc[mt][nt].y);
                *(float2*)&C[(size_t)(r + 8) * N + c] =
                    make_float2(acc[mt][nt].z, acc[mt][nt].w);
            }
        }
    }
}

// ---------------------------------------------------------------------------
// fp16 flash attention (R13 winner, unchanged)
// ---------------------------------------------------------------------------
__global__ __launch_bounds__(128) void attn3()
{
    extern __shared__ __align__(16) char smem[];
    uint32_t sKu = sm_u32(smem);           // 64 rows x 256B (swizzled)
    uint32_t sVu = sKu + 16384;            // 64 rows x 256B (swizzled)

    const int tid = threadIdx.x;
    const int wid = tid >> 5, lane = tid & 31;
    const int gid = lane >> 2, tig = lane & 3;
    const int qt = gridDim.x - 1 - blockIdx.x;   // big tiles first
    const int bh = blockIdx.y;
    const int b = bh >> 4, h = bh & 15, kvh = h >> 2;
    const int qb = qt * 64;

    const int lx = lane & 7;
    const int lb16 = (lane >> 4) & 1;
    const int lb8 = (lane >> 3) & 1;

    const __half* Kg0 = g_qkvh + (size_t)(b * SEQ) * QKVD + 2048 + kvh * HD;
    const __half* Vg0 = Kg0 + 512;

    uint32_t qf[8][4];
    {
        const __half* Qg = g_qkvh + (size_t)(b * SEQ + qb + wid * 16) * QKVD + h * HD;
#pragma unroll
        for (int ks = 0; ks < 8; ks++) {
            qf[ks][0] = *(const uint32_t*)&Qg[(size_t)gid * QKVD + 16 * ks + 2 * tig];
            qf[ks][1] = *(const uint32_t*)&Qg[(size_t)(gid + 8) * QKVD + 16 * ks + 2 * tig];
            qf[ks][2] = *(const uint32_t*)&Qg[(size_t)gid * QKVD + 16 * ks + 8 + 2 * tig];
            qf[ks][3] = *(const uint32_t*)&Qg[(size_t)(gid + 8) * QKVD + 16 * ks + 8 + 2 * tig];
        }
    }

    auto ld_K = [&](int kt) {
        const __half* Kg = Kg0 + (size_t)(kt * 64) * QKVD;
#pragma unroll
        for (int i = 0; i < 8; i++) {
            int id = tid + i * 128;
            int r = id >> 4, c = id & 15;
            cp_async16(sKu + (uint32_t)(r * 256) + (swz(c, r) << 4),
                       Kg + (size_t)r * QKVD + c * 8);
        }
        cp_commit();
    };
    auto ld_V = [&](int kt) {
        const __half* Vg = Vg0 + (size_t)(kt * 64) * QKVD;
#pragma unroll
        for (int i = 0; i < 8; i++) {
            int id = tid + i * 128;
            int r = id >> 4, c = id & 15;
            cp_async16(sVu + (uint32_t)(r * 256) + (swz(c, r) << 4),
                       Vg + (size_t)r * QKVD + c * 8);
        }
        cp_commit();
    };

    float4 of[16];
#pragma unroll
    for (int i = 0; i < 16; i++) of[i] = make_float4(0.f, 0.f, 0.f, 0.f);
    float m0 = -FLT_MAX, m1 = -FLT_MAX, l0 = 0.f, l1 = 0.f;

    ld_K(0);
    ld_V(0);

    for (int kt = 0; kt <= qt; kt++) {
        const int kbase = kt * 64;
        const int ktn = (kt + 1 <= qt) ? kt + 1 : qt;

        cp_wait<1>();
        __syncthreads();

        float4 s[8];
#pragma unroll
        for (int nt = 0; nt < 8; nt++) s[nt] = make_float4(0.f, 0.f, 0.f, 0.f);
#pragma unroll
        for (int ks = 0; ks < 8; ks++) {
            const uint32_t chunk = (uint32_t)(2 * ks + lb8);
#pragma unroll
            for (int half = 0; half < 2; half++) {
                const int row0 = (2 * half) * 16 + lb16 * 8 + lx;
                const int row1 = (2 * half + 1) * 16 + lb16 * 8 + lx;
                uint32_t kb0[4], kb1[4];
                ldsm_x4(kb0, sKu + (uint32_t)(row0 * 256) + (swz(chunk, row0) << 4));
                ldsm_x4(kb1, sKu + (uint32_t)(row1 * 256) + (swz(chunk, row1) << 4));
                mma_f16(s[4*half],     qf[ks], kb0[0], kb0[1]);
                mma_f16(s[4*half + 1], qf[ks], kb0[2], kb0[3]);
                mma_f16(s[4*half + 2], qf[ks], kb1[0], kb1[1]);
                mma_f16(s[4*half + 3], qf[ks], kb1[2], kb1[3]);
            }
        }
        __syncthreads();
        ld_K(ktn);

        if (kt == qt) {
            int r0 = qb + wid * 16 + gid;
#pragma unroll
            for (int nt = 0; nt < 8; nt++) {
                int c = kbase + nt * 8 + 2 * tig;
                if (c > r0)         s[nt].x = -FLT_MAX;
                if (c + 1 > r0)     s[nt].y = -FLT_MAX;
                if (c > r0 + 8)     s[nt].z = -FLT_MAX;
                if (c + 1 > r0 + 8) s[nt].w = -FLT_MAX;
            }
        }

        float mt0 = -FLT_MAX, mt1 = -FLT_MAX;
#pragma unroll
        for (int nt = 0; nt < 8; nt++) {
            mt0 = fmaxf(mt0, fmaxf(s[nt].x, s[nt].y));
            mt1 = fmaxf(mt1, fmaxf(s[nt].z, s[nt].w));
        }
        mt0 = fmaxf(mt0, __shfl_xor_sync(0xffffffffu, mt0, 1));
        mt0 = fmaxf(mt0, __shfl_xor_sync(0xffffffffu, mt0, 2));
        mt1 = fmaxf(mt1, __shfl_xor_sync(0xffffffffu, mt1, 1));
        mt1 = fmaxf(mt1, __shfl_xor_sync(0xffffffffu, mt1, 2));

        float mn0 = fmaxf(m0, mt0), mn1 = fmaxf(m1, mt1);
        float a0 = exp2f(m0 - mn0), a1 = exp2f(m1 - mn1);
        float sum0 = 0.f, sum1 = 0.f;
#pragma unroll
        for (int nt = 0; nt < 8; nt++) {
            s[nt].x = exp2f(s[nt].x - mn0);
            s[nt].y = exp2f(s[nt].y - mn0);
            s[nt].z = exp2f(s[nt].z - mn1);
            s[nt].w = exp2f(s[nt].w - mn1);
            sum0 += s[nt].x + s[nt].y;
            sum1 += s[nt].z + s[nt].w;
        }
        sum0 += __shfl_xor_sync(0xffffffffu, sum0, 1);
        sum0 += __shfl_xor_sync(0xffffffffu, sum0, 2);
        sum1 += __shfl_xor_sync(0xffffffffu, sum1, 1);
        sum1 += __shfl_xor_sync(0xffffffffu, sum1, 2);

        l0 = l0 * a0 + sum0;
        l1 = l1 * a1 + sum1;
        m0 = mn0; m1 = mn1;
#pragma unroll
        for (int dt = 0; dt < 16; dt++) {
            of[dt].x *= a0; of[dt].y *= a0;
            of[dt].z *= a1; of[dt].w *= a1;
        }

        uint32_t ph[4][4];
#pragma unroll
        for (int kv = 0; kv < 4; kv++) {
            ph[kv][0] = pack2(s[2*kv].x,     s[2*kv].y);
            ph[kv][1] = pack2(s[2*kv].z,     s[2*kv].w);
            ph[kv][2] = pack2(s[2*kv + 1].x, s[2*kv + 1].y);
            ph[kv][3] = pack2(s[2*kv + 1].z, s[2*kv + 1].w);
        }

        cp_wait<1>();
        __syncthreads();

#pragma unroll
        for (int kv = 0; kv < 4; kv++) {
            const int row = kv * 16 + lb8 * 8 + lx;
            const uint32_t va = sVu + (uint32_t)(row * 256);
#pragma unroll
            for (int nb = 0; nb < 8; nb++) {
                uint32_t vb[4];
                ldsm_x4t(vb, va + (swz((uint32_t)(2 * nb + lb16), row) << 4));
                mma_f16(of[2*nb],     ph[kv], vb[0], vb[1]);
                mma_f16(of[2*nb + 1], ph[kv], vb[2], vb[3]);
            }
        }
        __syncthreads();
        ld_V(ktn);
    }
    cp_wait<0>();

    float inv0 = 1.0f / l0, inv1 = 1.0f / l1;
    __half* Yg = g_yh + (size_t)(b * SEQ + qb + wid * 16 + gid) * DIM + h * HD;
#pragma unroll
    for (int dt = 0; dt < 16; dt++) {
        int c = dt * 8 + 2 * tig;
        *(uint32_t*)&Yg[c]           = pack2(of[dt].x * inv0, of[dt].y * inv0);
        *(uint32_t*)&Yg[8 * DIM + c] = pack2(of[dt].z * inv1, of[dt].w * inv1);
    }
}

// ---------------------------------------------------------------------------
extern "C" void kernel_launch(void* const* d_in, const int* in_sizes, int n_in,
                              void* d_out, int out_size)
{
    (void)in_sizes; (void)n_in; (void)out_size;
    const float* x  = (const float*)d_in[0];
    const float* qg = (const float*)d_in[1];
    const float* Wq = (const float*)d_in[2];
    const float* Wk = (const float*)d_in[3];
    const float* Wv = (const float*)d_in[4];
    const float* Wp = (const float*)d_in[5];
    float* out = (float*)d_out;

    __half *qkvh, *xh, *wqkvh, *wph, *yh;
    cudaGetSymbolAddress((void**)&qkvh, g_qkvh);
    cudaGetSymbolAddress((void**)&xh, g_xh);
    cudaGetSymbolAddress((void**)&wqkvh, g_wqkvh);
    cudaGetSymbolAddress((void**)&wph, g_wph);
    cudaGetSymbolAddress((void**)&yh, g_yh);

    // launch 1: fp16 conversion + rope table
    prep_all<<<BLH_X + BLH_WQ + BLH_WK + BLH_WV + BLH_WP + BLH_TB, 256>>>(x, Wq, Wk, Wv, Wp);

    size_t gsm = 2 * (size_t)STAGE_B;  // 65536 (2-stage)
    cudaFuncSetAttribute(gemm_h<__half>, cudaFuncAttributeMaxDynamicSharedMemorySize, (int)gsm);
    cudaFuncSetAttribute(gemm_h<float>,  cudaFuncAttributeMaxDynamicSharedMemorySize, (int)gsm);

    // launch 2: fused QKV projection (fp16 in, fp16 out)
    gemm_h<__half><<<dim3(QKVD / 128, BT / 128), 128, gsm>>>(xh, wqkvh, qkvh, QKVD, DIM);

    // launch 3: norm + rope + gain, in-place fp16 (q,k only), half2 path
    norm_rope4<<<(BT * 20) / 8, 256>>>(qg);

    // launch 4: flash attention (profiled slot)
    size_t asm_ = 32768;
    cudaFuncSetAttribute(attn3, cudaFuncAttributeMaxDynamicSharedMemorySize, (int)asm_);
    attn3<<<dim3(SEQ / 64, BATCH * NHEADS), 128, asm_>>>();

    // launch 5: output projection (fp16 in, fp32 out)
    gemm_h<float><<<dim3(DIM / 128, BT / 128), 128, gsm>>>(yh, wph, out, DIM, DIM);
}

// round 16
// speedup vs baseline: 1.0796x; 1.0796x over previous
#include <cuda_runtime.h>
#include <cuda_fp16.h>
#include <math.h>
#include <float.h>
#include <stdint.h>

#define DIM 2048
#define QKVD 3072
#define NHEADS 16
#define NKV 4
#define HD 128
#define BATCH 2
#define SEQ 2048
#define BT (BATCH*SEQ)     // 4096
#define KVDIM 512

// Scratch (__device__ globals per allocation-free rule)
__device__ __align__(16) __half g_qkvh[(size_t)BT*QKVD];   // qkv (fp16)
__device__ __align__(16) __half g_xh[(size_t)BT*DIM];
__device__ __align__(16) __half g_wqkvh[(size_t)QKVD*DIM];
__device__ __align__(16) __half g_wph[(size_t)DIM*DIM];
__device__ __align__(16) __half g_yh[(size_t)BT*DIM];      // attention output (fp16)
__device__ __align__(16) float2 g_tab[SEQ*64];

// ---------------------------------------------------------------------------
// helpers
// ---------------------------------------------------------------------------
__device__ __forceinline__ uint32_t pack2(float a, float b) {
    __half2 h = __floats2half2_rn(a, b);
    return *(uint32_t*)&h;
}

__device__ __forceinline__ void mma_f16(float4& c, const uint32_t* a,
                                        uint32_t b0, uint32_t b1) {
    asm volatile(
        "mma.sync.aligned.m16n8k16.row.col.f32.f16.f16.f32 "
        "{%0,%1,%2,%3}, {%4,%5,%6,%7}, {%8,%9}, {%0,%1,%2,%3};"
        : "+f"(c.x), "+f"(c.y), "+f"(c.z), "+f"(c.w)
        : "r"(a[0]), "r"(a[1]), "r"(a[2]), "r"(a[3]), "r"(b0), "r"(b1));
}

__device__ __forceinline__ void cp_async16(uint32_t s, const void* g) {
    asm volatile("cp.async.cg.shared.global [%0], [%1], 16;" :: "r"(s), "l"(g));
}
__device__ __forceinline__ void cp_commit() {
    asm volatile("cp.async.commit_group;");
}
template<int N> __device__ __forceinline__ void cp_wait() {
    asm volatile("cp.async.wait_group %0;" :: "n"(N));
}

__device__ __forceinline__ uint32_t sm_u32(const void* p) {
    return (uint32_t)__cvta_generic_to_shared(p);
}

__device__ __forceinline__ void ldsm_x4(uint32_t* r, uint32_t addr) {
    asm volatile("ldmatrix.sync.aligned.m8n8.x4.shared.b16 {%0,%1,%2,%3}, [%4];"
                 : "=r"(r[0]), "=r"(r[1]), "=r"(r[2]), "=r"(r[3]) : "r"(addr));
}
__device__ __forceinline__ void ldsm_x4t(uint32_t* r, uint32_t addr) {
    asm volatile("ldmatrix.sync.aligned.m8n8.x4.trans.shared.b16 {%0,%1,%2,%3}, [%4];"
                 : "=r"(r[0]), "=r"(r[1]), "=r"(r[2]), "=r"(r[3]) : "r"(addr));
}

// swizzle a 16B-chunk index within a row (toggles low 3 bits only)
__device__ __forceinline__ uint32_t swz(uint32_t c, uint32_t r) {
    return (c & ~7u) | ((c ^ (r & 7u)) & 7u);
}

// ---------------------------------------------------------------------------
// prep_all: fp32 -> fp16 conversion of x + weights, plus RoPE table.
// ---------------------------------------------------------------------------
#define BLH_X  4096
#define BLH_WQ 2048
#define BLH_WK 512
#define BLH_WV 512
#define BLH_WP 2048
#define BLH_TB 512

__global__ __launch_bounds__(256) void prep_all(const float* __restrict__ x,
                                                const float* __restrict__ Wq,
                                                const float* __restrict__ Wk,
                                                const float* __restrict__ Wv,
                                                const float* __restrict__ Wp)
{
    int blk = blockIdx.x;
    const float* src;
    __half* dst;
    if (blk < BLH_X)                  { src = x;  dst = g_xh; }
    else if ((blk -= BLH_X) < BLH_WQ) { src = Wq; dst = g_wqkvh; }
    else if ((blk -= BLH_WQ) < BLH_WK){ src = Wk; dst = g_wqkvh + (size_t)2048 * DIM; }
    else if ((blk -= BLH_WK) < BLH_WV){ src = Wv; dst = g_wqkvh + (size_t)2560 * DIM; }
    else if ((blk -= BLH_WV) < BLH_WP){ src = Wp; dst = g_wph; }
    else {
        blk -= BLH_WP;   // rope table
        int idx = blk * 256 + threadIdx.x;
        int t = idx >> 6, j = idx & 63;
        float inv_freq = expf(-(float)j * (9.210340371976184f / 64.0f));
        float ang = (float)t * inv_freq;
        float sn, cs;
        sincosf(ang, &sn, &cs);
        g_tab[idx] = make_float2(cs, sn);
        return;
    }
    int i = (blk * 256 + threadIdx.x) * 8;
    float4 v0 = *(const float4*)(src + i);
    float4 v1 = *(const float4*)(src + i + 4);
    uint4 o;
    o.x = pack2(v0.x, v0.y);
    o.y = pack2(v0.z, v0.w);
    o.z = pack2(v1.x, v1.y);
    o.w = pack2(v1.z, v1.w);
    *(uint4*)(dst + i) = o;
}

// ---------------------------------------------------------------------------
// warp-per-unit norm/rope, in-place on fp16 g_qkvh, half2-vectorized.
// ---------------------------------------------------------------------------
__global__ __launch_bounds__(256) void norm_rope4(const float* __restrict__ q_gain)
{
    int u = blockIdx.x * 8 + (threadIdx.x >> 5);
    int lane = threadIdx.x & 31;
    int row = u / 20;
    int h = u - row * 20;

    __half2* p2;
    float g;
    if (h < NHEADS) {
        p2 = (__half2*)(g_qkvh + (size_t)row * QKVD + h * HD);
        g = q_gain[h] * 0.08838834764831845f * 1.4426950408889634f;
    } else {
        p2 = (__half2*)(g_qkvh + (size_t)row * QKVD + 2048 + (h - NHEADS) * HD);
        g = 1.0f;
    }

    __half2 ha = p2[lane];
    __half2 hb = p2[lane + 32];
    float2 a = __half22float2(ha);
    float2 b = __half22float2(hb);

    float ss = a.x * a.x + a.y * a.y + b.x * b.x + b.y * b.y;
#pragma unroll
    for (int o = 16; o; o >>= 1) ss += __shfl_xor_sync(0xffffffffu, ss, o);
    float r = rsqrtf(ss * (1.0f / 128.0f) + 1.1920928955078125e-07f);
    a.x *= r; a.y *= r; b.x *= r; b.y *= r;

    int t = row & (SEQ - 1);
    float2 cs0 = g_tab[t * 64 + 2 * lane];
    float2 cs1 = g_tab[t * 64 + 2 * lane + 1];

    float y1x = (a.x * cs0.x + b.x * cs0.y) * g;
    float y2x = (-a.x * cs0.y + b.x * cs0.x) * g;
    float y1y = (a.y * cs1.x + b.y * cs1.y) * g;
    float y2y = (-a.y * cs1.y + b.y * cs1.x) * g;

    p2[lane]      = __floats2half2_rn(y1x, y1y);
    p2[lane + 32] = __floats2half2_rn(y2x, y2y);
}

// ---------------------------------------------------------------------------
// fp16 HMMA GEMM: C[M,N] = A[M,K](f16) @ B[N,K](f16)^T, OutT in {float,__half}
// CTA tile 128x128x64, 256 threads (8 warps 2x4, warp tile 64x32).
// acc = 64 f32/thread -> ~130 regs natural -> 2 CTAs/SM = 16 warps/SM.
// 3-stage cp.async pipeline, 32KB/stage (96KB smem/CTA).
// ---------------------------------------------------------------------------
#define STAGE_B 32768

template<typename OutT>
__global__ __launch_bounds__(256, 2) void gemm_h(const __half* __restrict__ A,
                                                 const __half* __restrict__ B,
                                                 OutT* __restrict__ C,
                                                 int N, int K)
{
    extern __shared__ __align__(16) char smem[];
    const int tid = threadIdx.x;
    const int wid = tid >> 5, lane = tid & 31;
    const int wm = wid >> 2, wn = wid & 3;     // 2 x 4 warp grid
    const int gid = lane >> 2, tig = lane & 3;
    const int row0 = blockIdx.y * 128, col0 = blockIdx.x * 128;
    uint32_t sbase = sm_u32(smem);

    float4 acc[4][4];                          // warp tile 64x32
#pragma unroll
    for (int i = 0; i < 4; i++)
#pragma unroll
        for (int j = 0; j < 4; j++) acc[i][j] = make_float4(0.f, 0.f, 0.f, 0.f);

    auto ld_tile = [&](int t, int s) {
        int k0 = t << 6;
        uint32_t sa = sbase + s * STAGE_B;
        uint32_t sb = sa + 16384;
        const __half* ga = A + (size_t)row0 * K + k0;
        const __half* gb = B + (size_t)col0 * K + k0;
#pragma unroll
        for (int i = 0; i < 4; i++) {
            int id = tid + i * 256;            // 0..1023
            int r = id >> 3, c = id & 7;
            uint32_t off = (uint32_t)(r * 128 + ((c ^ (r & 7)) << 4));
            cp_async16(sa + off, ga + (size_t)r * K + c * 8);
            cp_async16(sb + off, gb + (size_t)r * K + c * 8);
        }
        cp_commit();
    };

    const int lx = lane & 7;
    const int l15 = lane & 15;
    const int lb16 = (lane >> 4) & 1;
    const int lb8 = (lane >> 3) & 1;

    const int nT = K >> 6;
    ld_tile(0, 0);
    ld_tile(1, 1);

    for (int t = 0; t < nT; t++) {
        if (t + 1 < nT) cp_wait<1>(); else cp_wait<0>();
        __syncthreads();
        if (t + 2 < nT) ld_tile(t + 2, (t + 2) % 3);

        uint32_t sa = sbase + (t % 3) * STAGE_B;
        uint32_t sb = sa + 16384;
#pragma unroll
        for (int ks = 0; ks < 4; ks++) {
            uint32_t a[4][4], b[2][4];
#pragma unroll
            for (int mt = 0; mt < 4; mt++) {
                int row = wm * 64 + mt * 16 + l15;
                uint32_t chunk = (uint32_t)(2 * ks + lb16);
                ldsm_x4(a[mt], sa + (uint32_t)(row * 128)
                               + (((chunk ^ (row & 7)) & 7) << 4));
            }
#pragma unroll
            for (int nb = 0; nb < 2; nb++) {
                int row = wn * 32 + nb * 16 + lb16 * 8 + lx;
                uint32_t chunk = (uint32_t)(2 * ks + lb8);
                ldsm_x4(b[nb], sb + (uint32_t)(row * 128)
                               + (((chunk ^ (row & 7)) & 7) << 4));
            }
#pragma unroll
            for (int mt = 0; mt < 4; mt++)
#pragma unroll
                for (int nb = 0; nb < 2; nb++) {
                    mma_f16(acc[mt][2*nb],     a[mt], b[nb][0], b[nb][1]);
                    mma_f16(acc[mt][2*nb + 1], a[mt], b[nb][2], b[nb][3]);
                }
        }
    }

#pragma unroll
    for (int mt = 0; mt < 4; mt++) {
        int r = row0 + wm * 64 + mt * 16 + gid;
#pragma unroll
        for (int nt = 0; nt < 4; nt++) {
            int c = col0 + wn * 32 + nt * 8 + tig * 2;
            if (sizeof(OutT) == 2) {
                *(uint32_t*)&C[(size_t)r * N + c] = pack2(acc[mt][nt].x, acc[mt][nt].y);
                *(uint32_t*)&C[(size_t)(r + 8) * N + c] = pack2(acc[mt][nt].z, acc[mt][nt].w);
            } else {
                *(float2*)&C[(size_t)r * N + c] =
                    make_float2(acc[mt][nt].x, acc[mt][nt].y);
                *(float2*)&C[(size_t)(r + 8) * N + c] =
                    make_float2(acc[mt][nt].z, acc[mt][nt].w);
            }
        }
    }
}

// ---------------------------------------------------------------------------
// fp16 flash attention (R13 winner, unchanged)
// ---------------------------------------------------------------------------
__global__ __launch_bounds__(128) void attn3()
{
    extern __shared__ __align__(16) char smem[];
    uint32_t sKu = sm_u32(smem);           // 64 rows x 256B (swizzled)
    uint32_t sVu = sKu + 16384;            // 64 rows x 256B (swizzled)

    const int tid = threadIdx.x;
    const int wid = tid >> 5, lane = tid & 31;
    const int gid = lane >> 2, tig = lane & 3;
    const int qt = gridDim.x - 1 - blockIdx.x;   // big tiles first
    const int bh = blockIdx.y;
    const int b = bh >> 4, h = bh & 15, kvh = h >> 2;
    const int qb = qt * 64;

    const int lx = lane & 7;
    const int lb16 = (lane >> 4) & 1;
    const int lb8 = (lane >> 3) & 1;

    const __half* Kg0 = g_qkvh + (size_t)(b * SEQ) * QKVD + 2048 + kvh * HD;
    const __half* Vg0 = Kg0 + 512;

    uint32_t qf[8][4];
    {
        const __half* Qg = g_qkvh + (size_t)(b * SEQ + qb + wid * 16) * QKVD + h * HD;
#pragma unroll
        for (int ks = 0; ks < 8; ks++) {
            qf[ks][0] = *(const uint32_t*)&Qg[(size_t)gid * QKVD + 16 * ks + 2 * tig];
            qf[ks][1] = *(const uint32_t*)&Qg[(size_t)(gid + 8) * QKVD + 16 * ks + 2 * tig];
            qf[ks][2] = *(const uint32_t*)&Qg[(size_t)gid * QKVD + 16 * ks + 8 + 2 * tig];
            qf[ks][3] = *(const uint32_t*)&Qg[(size_t)(gid + 8) * QKVD + 16 * ks + 8 + 2 * tig];
        }
    }

    auto ld_K = [&](int kt) {
        const __half* Kg = Kg0 + (size_t)(kt * 64) * QKVD;
#pragma unroll
        for (int i = 0; i < 8; i++) {
            int id = tid + i * 128;
            int r = id >> 4, c = id & 15;
            cp_async16(sKu + (uint32_t)(r * 256) + (swz(c, r) << 4),
                       Kg + (size_t)r * QKVD + c * 8);
        }
        cp_commit();
    };
    auto ld_V = [&](int kt) {
        const __half* Vg = Vg0 + (size_t)(kt * 64) * QKVD;
#pragma unroll
        for (int i = 0; i < 8; i++) {
            int id = tid + i * 128;
            int r = id >> 4, c = id & 15;
            cp_async16(sVu + (uint32_t)(r * 256) + (swz(c, r) << 4),
                       Vg + (size_t)r * QKVD + c * 8);
        }
        cp_commit();
    };

    float4 of[16];
#pragma unroll
    for (int i = 0; i < 16; i++) of[i] = make_float4(0.f, 0.f, 0.f, 0.f);
    float m0 = -FLT_MAX, m1 = -FLT_MAX, l0 = 0.f, l1 = 0.f;

    ld_K(0);
    ld_V(0);

    for (int kt = 0; kt <= qt; kt++) {
        const int kbase = kt * 64;
        const int ktn = (kt + 1 <= qt) ? kt + 1 : qt;

        cp_wait<1>();
        __syncthreads();

        float4 s[8];
#pragma unroll
        for (int nt = 0; nt < 8; nt++) s[nt] = make_float4(0.f, 0.f, 0.f, 0.f);
#pragma unroll
        for (int ks = 0; ks < 8; ks++) {
            const uint32_t chunk = (uint32_t)(2 * ks + lb8);
#pragma unroll
            for (int half = 0; half < 2; half++) {
                const int row0 = (2 * half) * 16 + lb16 * 8 + lx;
                const int row1 = (2 * half + 1) * 16 + lb16 * 8 + lx;
                uint32_t kb0[4], kb1[4];
                ldsm_x4(kb0, sKu + (uint32_t)(row0 * 256) + (swz(chunk, row0) << 4));
                ldsm_x4(kb1, sKu + (uint32_t)(row1 * 256) + (swz(chunk, row1) << 4));
                mma_f16(s[4*half],     qf[ks], kb0[0], kb0[1]);
                mma_f16(s[4*half + 1], qf[ks], kb0[2], kb0[3]);
                mma_f16(s[4*half + 2], qf[ks], kb1[0], kb1[1]);
                mma_f16(s[4*half + 3], qf[ks], kb1[2], kb1[3]);
            }
        }
        __syncthreads();
        ld_K(ktn);

        if (kt == qt) {
            int r0 = qb + wid * 16 + gid;
#pragma unroll
            for (int nt = 0; nt < 8; nt++) {
                int c = kbase + nt * 8 + 2 * tig;
                if (c > r0)         s[nt].x = -FLT_MAX;
                if (c + 1 > r0)     s[nt].y = -FLT_MAX;
                if (c > r0 + 8)     s[nt].z = -FLT_MAX;
                if (c + 1 > r0 + 8) s[nt].w = -FLT_MAX;
            }
        }

        float mt0 = -FLT_MAX, mt1 = -FLT_MAX;
#pragma unroll
        for (int nt = 0; nt < 8; nt++) {
            mt0 = fmaxf(mt0, fmaxf(s[nt].x, s[nt].y));
            mt1 = fmaxf(mt1, fmaxf(s[nt].z, s[nt].w));
        }
        mt0 = fmaxf(mt0, __shfl_xor_sync(0xffffffffu, mt0, 1));
        mt0 = fmaxf(mt0, __shfl_xor_sync(0xffffffffu, mt0, 2));
        mt1 = fmaxf(mt1, __shfl_xor_sync(0xffffffffu, mt1, 1));
        mt1 = fmaxf(mt1, __shfl_xor_sync(0xffffffffu, mt1, 2));

        float mn0 = fmaxf(m0, mt0), mn1 = fmaxf(m1, mt1);
        float a0 = exp2f(m0 - mn0), a1 = exp2f(m1 - mn1);
        float sum0 = 0.f, sum1 = 0.f;
#pragma unroll
        for (int nt = 0; nt < 8; nt++) {
            s[nt].x = exp2f(s[nt].x - mn0);
            s[nt].y = exp2f(s[nt].y - mn0);
            s[nt].z = exp2f(s[nt].z - mn1);
            s[nt].w = exp2f(s[nt].w - mn1);
            sum0 += s[nt].x + s[nt].y;
            sum1 += s[nt].z + s[nt].w;
        }
        sum0 += __shfl_xor_sync(0xffffffffu, sum0, 1);
        sum0 += __shfl_xor_sync(0xffffffffu, sum0, 2);
        sum1 += __shfl_xor_sync(0xffffffffu, sum1, 1);
        sum1 += __shfl_xor_sync(0xffffffffu, sum1, 2);

        l0 = l0 * a0 + sum0;
        l1 = l1 * a1 + sum1;
        m0 = mn0; m1 = mn1;
#pragma unroll
        for (int dt = 0; dt < 16; dt++) {
            of[dt].x *= a0; of[dt].y *= a0;
            of[dt].z *= a1; of[dt].w *= a1;
        }

        uint32_t ph[4][4];
#pragma unroll
        for (int kv = 0; kv < 4; kv++) {
            ph[kv][0] = pack2(s[2*kv].x,     s[2*kv].y);
            ph[kv][1] = pack2(s[2*kv].z,     s[2*kv].w);
            ph[kv][2] = pack2(s[2*kv + 1].x, s[2*kv + 1].y);
            ph[kv][3] = pack2(s[2*kv + 1].z, s[2*kv + 1].w);
        }

        cp_wait<1>();
        __syncthreads();

#pragma unroll
        for (int kv = 0; kv < 4; kv++) {
            const int row = kv * 16 + lb8 * 8 + lx;
            const uint32_t va = sVu + (uint32_t)(row * 256);
#pragma unroll
            for (int nb = 0; nb < 8; nb++) {
                uint32_t vb[4];
                ldsm_x4t(vb, va + (swz((uint32_t)(2 * nb + lb16), row) << 4));
                mma_f16(of[2*nb],     ph[kv], vb[0], vb[1]);
                mma_f16(of[2*nb + 1], ph[kv], vb[2], vb[3]);
            }
        }
        __syncthreads();
        ld_V(ktn);
    }
    cp_wait<0>();

    float inv0 = 1.0f / l0, inv1 = 1.0f / l1;
    __half* Yg = g_yh + (size_t)(b * SEQ + qb + wid * 16 + gid) * DIM + h * HD;
#pragma unroll
    for (int dt = 0; dt < 16; dt++) {
        int c = dt * 8 + 2 * tig;
        *(uint32_t*)&Yg[c]           = pack2(of[dt].x * inv0, of[dt].y * inv0);
        *(uint32_t*)&Yg[8 * DIM + c] = pack2(of[dt].z * inv1, of[dt].w * inv1);
    }
}

// ---------------------------------------------------------------------------
extern "C" void kernel_launch(void* const* d_in, const int* in_sizes, int n_in,
                              void* d_out, int out_size)
{
    (void)in_sizes; (void)n_in; (void)out_size;
    const float* x  = (const float*)d_in[0];
    const float* qg = (const float*)d_in[1];
    const float* Wq = (const float*)d_in[2];
    const float* Wk = (const float*)d_in[3];
    const float* Wv = (const float*)d_in[4];
    const float* Wp = (const float*)d_in[5];
    float* out = (float*)d_out;

    __half *qkvh, *xh, *wqkvh, *wph, *yh;
    cudaGetSymbolAddress((void**)&qkvh, g_qkvh);
    cudaGetSymbolAddress((void**)&xh, g_xh);
    cudaGetSymbolAddress((void**)&wqkvh, g_wqkvh);
    cudaGetSymbolAddress((void**)&wph, g_wph);
    cudaGetSymbolAddress((void**)&yh, g_yh);

    // launch 1: fp16 conversion + rope table
    prep_all<<<BLH_X + BLH_WQ + BLH_WK + BLH_WV + BLH_WP + BLH_TB, 256>>>(x, Wq, Wk, Wv, Wp);

    size_t gsm = 3 * (size_t)STAGE_B;  // 98304 (3-stage)
    cudaFuncSetAttribute(gemm_h<__half>, cudaFuncAttributeMaxDynamicSharedMemorySize, (int)gsm);
    cudaFuncSetAttribute(gemm_h<float>,  cudaFuncAttributeMaxDynamicSharedMemorySize, (int)gsm);

    // launch 2: fused QKV projection (fp16 in, fp16 out)
    gemm_h<__half><<<dim3(QKVD / 128, BT / 128), 256, gsm>>>(xh, wqkvh, qkvh, QKVD, DIM);

    // launch 3: norm + rope + gain, in-place fp16 (q,k only), half2 path
    norm_rope4<<<(BT * 20) / 8, 256>>>(qg);

    // launch 4: flash attention (profiled slot)
    size_t asm_ = 32768;
    cudaFuncSetAttribute(attn3, cudaFuncAttributeMaxDynamicSharedMemorySize, (int)asm_);
    attn3<<<dim3(SEQ / 64, BATCH * NHEADS), 128, asm_>>>();

    // launch 5: output projection (fp16 in, fp32 out)
    gemm_h<float><<<dim3(DIM / 128, BT / 128), 256, gsm>>>(yh, wph, out, DIM, DIM);
}

// round 17
// speedup vs baseline: 1.0926x; 1.0121x over previous
#include <cuda_runtime.h>
#include <cuda_fp16.h>
#include <math.h>
#include <float.h>
#include <stdint.h>

#define DIM 2048
#define QKVD 3072
#define NHEADS 16
#define NKV 4
#define HD 128
#define BATCH 2
#define SEQ 2048
#define BT (BATCH*SEQ)     // 4096
#define KVDIM 512

// Scratch (__device__ globals per allocation-free rule)
__device__ __align__(16) __half g_qkvh[(size_t)BT*QKVD];   // qkv (fp16)
__device__ __align__(16) __half g_xh[(size_t)BT*DIM];
__device__ __align__(16) __half g_wqkvh[(size_t)QKVD*DIM];
__device__ __align__(16) __half g_wph[(size_t)DIM*DIM];
__device__ __align__(16) __half g_yh[(size_t)BT*DIM];      // attention output (fp16)
__device__ __align__(16) float2 g_tab[SEQ*64];

// ---------------------------------------------------------------------------
// helpers
// ---------------------------------------------------------------------------
__device__ __forceinline__ uint32_t pack2(float a, float b) {
    __half2 h = __floats2half2_rn(a, b);
    return *(uint32_t*)&h;
}

__device__ __forceinline__ void mma_f16(float4& c, const uint32_t* a,
                                        uint32_t b0, uint32_t b1) {
    asm volatile(
        "mma.sync.aligned.m16n8k16.row.col.f32.f16.f16.f32 "
        "{%0,%1,%2,%3}, {%4,%5,%6,%7}, {%8,%9}, {%0,%1,%2,%3};"
        : "+f"(c.x), "+f"(c.y), "+f"(c.z), "+f"(c.w)
        : "r"(a[0]), "r"(a[1]), "r"(a[2]), "r"(a[3]), "r"(b0), "r"(b1));
}

__device__ __forceinline__ void cp_async16(uint32_t s, const void* g) {
    asm volatile("cp.async.cg.shared.global [%0], [%1], 16;" :: "r"(s), "l"(g));
}
__device__ __forceinline__ void cp_commit() {
    asm volatile("cp.async.commit_group;");
}
template<int N> __device__ __forceinline__ void cp_wait() {
    asm volatile("cp.async.wait_group %0;" :: "n"(N));
}

__device__ __forceinline__ uint32_t sm_u32(const void* p) {
    return (uint32_t)__cvta_generic_to_shared(p);
}

__device__ __forceinline__ void ldsm_x4(uint32_t* r, uint32_t addr) {
    asm volatile("ldmatrix.sync.aligned.m8n8.x4.shared.b16 {%0,%1,%2,%3}, [%4];"
                 : "=r"(r[0]), "=r"(r[1]), "=r"(r[2]), "=r"(r[3]) : "r"(addr));
}
__device__ __forceinline__ void ldsm_x4t(uint32_t* r, uint32_t addr) {
    asm volatile("ldmatrix.sync.aligned.m8n8.x4.trans.shared.b16 {%0,%1,%2,%3}, [%4];"
                 : "=r"(r[0]), "=r"(r[1]), "=r"(r[2]), "=r"(r[3]) : "r"(addr));
}

// swizzle a 16B-chunk index within a row (toggles low 3 bits only)
__device__ __forceinline__ uint32_t swz(uint32_t c, uint32_t r) {
    return (c & ~7u) | ((c ^ (r & 7u)) & 7u);
}

// ---------------------------------------------------------------------------
// prep_all: fp32 -> fp16 conversion of x + weights, plus RoPE table.
// ---------------------------------------------------------------------------
#define BLH_X  4096
#define BLH_WQ 2048
#define BLH_WK 512
#define BLH_WV 512
#define BLH_WP 2048
#define BLH_TB 512

__global__ __launch_bounds__(256) void prep_all(const float* __restrict__ x,
                                                const float* __restrict__ Wq,
                                                const float* __restrict__ Wk,
                                                const float* __restrict__ Wv,
                                                const float* __restrict__ Wp)
{
    int blk = blockIdx.x;
    const float* src;
    __half* dst;
    if (blk < BLH_X)                  { src = x;  dst = g_xh; }
    else if ((blk -= BLH_X) < BLH_WQ) { src = Wq; dst = g_wqkvh; }
    else if ((blk -= BLH_WQ) < BLH_WK){ src = Wk; dst = g_wqkvh + (size_t)2048 * DIM; }
    else if ((blk -= BLH_WK) < BLH_WV){ src = Wv; dst = g_wqkvh + (size_t)2560 * DIM; }
    else if ((blk -= BLH_WV) < BLH_WP){ src = Wp; dst = g_wph; }
    else {
        blk -= BLH_WP;   // rope table
        int idx = blk * 256 + threadIdx.x;
        int t = idx >> 6, j = idx & 63;
        float inv_freq = expf(-(float)j * (9.210340371976184f / 64.0f));
        float ang = (float)t * inv_freq;
        float sn, cs;
        sincosf(ang, &sn, &cs);
        g_tab[idx] = make_float2(cs, sn);
        return;
    }
    int i = (blk * 256 + threadIdx.x) * 8;
    float4 v0 = *(const float4*)(src + i);
    float4 v1 = *(const float4*)(src + i + 4);
    uint4 o;
    o.x = pack2(v0.x, v0.y);
    o.y = pack2(v0.z, v0.w);
    o.z = pack2(v1.x, v1.y);
    o.w = pack2(v1.z, v1.w);
    *(uint4*)(dst + i) = o;
}

// ---------------------------------------------------------------------------
// warp-per-unit norm/rope for K HEADS ONLY (q fused into attention).
// unit u -> row u/4, k head u%4. In-place on fp16 g_qkvh, half2-vectorized.
// ---------------------------------------------------------------------------
__global__ __launch_bounds__(256) void norm_k()
{
    int u = blockIdx.x * 8 + (threadIdx.x >> 5);
    int lane = threadIdx.x & 31;
    int row = u >> 2;
    int h = u & 3;

    __half2* p2 = (__half2*)(g_qkvh + (size_t)row * QKVD + 2048 + h * HD);

    __half2 ha = p2[lane];
    __half2 hb = p2[lane + 32];
    float2 a = __half22float2(ha);
    float2 b = __half22float2(hb);

    float ss = a.x * a.x + a.y * a.y + b.x * b.x + b.y * b.y;
#pragma unroll
    for (int o = 16; o; o >>= 1) ss += __shfl_xor_sync(0xffffffffu, ss, o);
    float r = rsqrtf(ss * (1.0f / 128.0f) + 1.1920928955078125e-07f);
    a.x *= r; a.y *= r; b.x *= r; b.y *= r;

    int t = row & (SEQ - 1);
    float2 cs0 = g_tab[t * 64 + 2 * lane];
    float2 cs1 = g_tab[t * 64 + 2 * lane + 1];

    float y1x = a.x * cs0.x + b.x * cs0.y;
    float y2x = -a.x * cs0.y + b.x * cs0.x;
    float y1y = a.y * cs1.x + b.y * cs1.y;
    float y2y = -a.y * cs1.y + b.y * cs1.x;

    p2[lane]      = __floats2half2_rn(y1x, y1y);
    p2[lane + 32] = __floats2half2_rn(y2x, y2y);
}

// ---------------------------------------------------------------------------
// fp16 HMMA GEMM: C[M,N] = A[M,K](f16) @ B[N,K](f16)^T, OutT in {float,__half}
// CTA tile 128x128x64, 128 threads (4 warps 2x2, warp tile 64x64).
// 3-stage cp.async pipeline (proven R13 config).
// ---------------------------------------------------------------------------
#define STAGE_B 32768

template<typename OutT>
__global__ __launch_bounds__(128, 2) void gemm_h(const __half* __restrict__ A,
                                                 const __half* __restrict__ B,
                                                 OutT* __restrict__ C,
                                                 int N, int K)
{
    extern __shared__ __align__(16) char smem[];
    const int tid = threadIdx.x;
    const int wid = tid >> 5, lane = tid & 31;
    const int wm = wid >> 1, wn = wid & 1;
    const int gid = lane >> 2, tig = lane & 3;
    const int row0 = blockIdx.y * 128, col0 = blockIdx.x * 128;
    uint32_t sbase = sm_u32(smem);

    float4 acc[4][8];
#pragma unroll
    for (int i = 0; i < 4; i++)
#pragma unroll
        for (int j = 0; j < 8; j++) acc[i][j] = make_float4(0.f, 0.f, 0.f, 0.f);

    auto ld_tile = [&](int t, int s) {
        int k0 = t << 6;
        uint32_t sa = sbase + s * STAGE_B;
        uint32_t sb = sa + 16384;
        const __half* ga = A + (size_t)row0 * K + k0;
        const __half* gb = B + (size_t)col0 * K + k0;
#pragma unroll
        for (int i = 0; i < 8; i++) {
            int id = tid + i * 128;
            int r = id >> 3, c = id & 7;
            uint32_t off = (uint32_t)(r * 128 + ((c ^ (r & 7)) << 4));
            cp_async16(sa + off, ga + (size_t)r * K + c * 8);
            cp_async16(sb + off, gb + (size_t)r * K + c * 8);
        }
        cp_commit();
    };

    const int lx = lane & 7;
    const int l15 = lane & 15;
    const int lb16 = (lane >> 4) & 1;
    const int lb8 = (lane >> 3) & 1;

    const int nT = K >> 6;
    ld_tile(0, 0);
    ld_tile(1, 1);

    for (int t = 0; t < nT; t++) {
        if (t + 1 < nT) cp_wait<1>(); else cp_wait<0>();
        __syncthreads();
        if (t + 2 < nT) ld_tile(t + 2, (t + 2) % 3);

        uint32_t sa = sbase + (t % 3) * STAGE_B;
        uint32_t sb = sa + 16384;
#pragma unroll
        for (int ks = 0; ks < 4; ks++) {
            uint32_t a[4][4], b[4][4];
#pragma unroll
            for (int mt = 0; mt < 4; mt++) {
                int row = wm * 64 + mt * 16 + l15;
                uint32_t chunk = (uint32_t)(2 * ks + lb16);
                ldsm_x4(a[mt], sa + (uint32_t)(row * 128)
                               + (((chunk ^ (row & 7)) & 7) << 4));
            }
#pragma unroll
            for (int nb = 0; nb < 4; nb++) {
                int row = wn * 64 + nb * 16 + lb16 * 8 + lx;
                uint32_t chunk = (uint32_t)(2 * ks + lb8);
                ldsm_x4(b[nb], sb + (uint32_t)(row * 128)
                               + (((chunk ^ (row & 7)) & 7) << 4));
            }
#pragma unroll
            for (int mt = 0; mt < 4; mt++)
#pragma unroll
                for (int nb = 0; nb < 4; nb++) {
                    mma_f16(acc[mt][2*nb],     a[mt], b[nb][0], b[nb][1]);
                    mma_f16(acc[mt][2*nb + 1], a[mt], b[nb][2], b[nb][3]);
                }
        }
    }

#pragma unroll
    for (int mt = 0; mt < 4; mt++) {
        int r = row0 + wm * 64 + mt * 16 + gid;
#pragma unroll
        for (int nt = 0; nt < 8; nt++) {
            int c = col0 + wn * 64 + nt * 8 + tig * 2;
            if (sizeof(OutT) == 2) {
                *(uint32_t*)&C[(size_t)r * N + c] = pack2(acc[mt][nt].x, acc[mt][nt].y);
                *(uint32_t*)&C[(size_t)(r + 8) * N + c] = pack2(acc[mt][nt].z, acc[mt][nt].w);
            } else {
                *(float2*)&C[(size_t)r * N + c] =
                    make_float2(acc[mt][nt].x, acc[mt][nt].y);
                *(float2*)&C[(size_t)(r + 8) * N + c] =
                    make_float2(acc[mt][nt].z, acc[mt][nt].w);
            }
        }
    }
}

// ---------------------------------------------------------------------------
// fp16 flash attention (R13 structure) with FUSED q RMSNorm+RoPE+gain on the
// register-resident Q fragments (pairs (j, j+64) are lane-local: qf[ks] vs
// qf[ks+4]; row sum needs only a 4-lane quad shuffle). K/V loads are issued
// first so the prologue hides under them.
// ---------------------------------------------------------------------------
__global__ __launch_bounds__(128) void attn3(const float* __restrict__ qgain)
{
    extern __shared__ __align__(16) char smem[];
    uint32_t sKu = sm_u32(smem);           // 64 rows x 256B (swizzled)
    uint32_t sVu = sKu + 16384;            // 64 rows x 256B (swizzled)

    const int tid = threadIdx.x;
    const int wid = tid >> 5, lane = tid & 31;
    const int gid = lane >> 2, tig = lane & 3;
    const int qt = gridDim.x - 1 - blockIdx.x;   // big tiles first
    const int bh = blockIdx.y;
    const int b = bh >> 4, h = bh & 15, kvh = h >> 2;
    const int qb = qt * 64;

    const int lx = lane & 7;
    const int lb16 = (lane >> 4) & 1;
    const int lb8 = (lane >> 3) & 1;

    const __half* Kg0 = g_qkvh + (size_t)(b * SEQ) * QKVD + 2048 + kvh * HD;
    const __half* Vg0 = Kg0 + 512;

    auto ld_K = [&](int kt) {
        const __half* Kg = Kg0 + (size_t)(kt * 64) * QKVD;
#pragma unroll
        for (int i = 0; i < 8; i++) {
            int id = tid + i * 128;
            int r = id >> 4, c = id & 15;
            cp_async16(sKu + (uint32_t)(r * 256) + (swz(c, r) << 4),
                       Kg + (size_t)r * QKVD + c * 8);
        }
        cp_commit();
    };
    auto ld_V = [&](int kt) {
        const __half* Vg = Vg0 + (size_t)(kt * 64) * QKVD;
#pragma unroll
        for (int i = 0; i < 8; i++) {
            int id = tid + i * 128;
            int r = id >> 4, c = id & 15;
            cp_async16(sVu + (uint32_t)(r * 256) + (swz(c, r) << 4),
                       Vg + (size_t)r * QKVD + c * 8);
        }
        cp_commit();
    };

    // start K/V loads first so the q-norm prologue overlaps them
    ld_K(0);
    ld_V(0);

    // persistent Q fragments (raw fp16 from GEMM), then fused norm+rope+gain
    uint32_t qf[8][4];
    {
        const __half* Qg = g_qkvh + (size_t)(b * SEQ + qb + wid * 16) * QKVD + h * HD;
#pragma unroll
        for (int ks = 0; ks < 8; ks++) {
            qf[ks][0] = *(const uint32_t*)&Qg[(size_t)gid * QKVD + 16 * ks + 2 * tig];
            qf[ks][1] = *(const uint32_t*)&Qg[(size_t)(gid + 8) * QKVD + 16 * ks + 2 * tig];
            qf[ks][2] = *(const uint32_t*)&Qg[(size_t)gid * QKVD + 16 * ks + 8 + 2 * tig];
            qf[ks][3] = *(const uint32_t*)&Qg[(size_t)(gid + 8) * QKVD + 16 * ks + 8 + 2 * tig];
        }

        // sum of squares per row (rows gid, gid+8); 4 lanes share a row
        float ss0 = 0.f, ss1 = 0.f;
#pragma unroll
        for (int ks = 0; ks < 8; ks++) {
            float2 v0 = __half22float2(*(__half2*)&qf[ks][0]);
            float2 v1 = __half22float2(*(__half2*)&qf[ks][1]);
            float2 v2 = __half22float2(*(__half2*)&qf[ks][2]);
            float2 v3 = __half22float2(*(__half2*)&qf[ks][3]);
            ss0 += v0.x * v0.x + v0.y * v0.y + v2.x * v2.x + v2.y * v2.y;
            ss1 += v1.x * v1.x + v1.y * v1.y + v3.x * v3.x + v3.y * v3.y;
        }
        ss0 += __shfl_xor_sync(0xffffffffu, ss0, 1);
        ss0 += __shfl_xor_sync(0xffffffffu, ss0, 2);
        ss1 += __shfl_xor_sync(0xffffffffu, ss1, 1);
        ss1 += __shfl_xor_sync(0xffffffffu, ss1, 2);

        // fold gain * 1/sqrt(128) * log2(e) (base-2 softmax downstream)
        float g = __ldg(&qgain[h]) * (0.08838834764831845f * 1.4426950408889634f);
        float f0 = rsqrtf(ss0 * (1.0f / 128.0f) + 1.1920928955078125e-07f) * g;
        float f1 = rsqrtf(ss1 * (1.0f / 128.0f) + 1.1920928955078125e-07f) * g;

        const int t0 = qb + wid * 16 + gid;            // seq position of row 0
        const float2* tb0 = g_tab + t0 * 64;
        const float2* tb1 = tb0 + 8 * 64;              // row gid+8
#pragma unroll
        for (int ks = 0; ks < 4; ks++) {
#pragma unroll
            for (int r = 0; r < 4; r++) {
                int j = 16 * ks + 2 * tig + ((r >> 1) << 3);  // local col < 64
                const float2* tb = (r & 1) ? tb1 : tb0;
                float f = (r & 1) ? f1 : f0;
                float2 a  = __half22float2(*(__half2*)&qf[ks][r]);      // x1 pair
                float2 bb = __half22float2(*(__half2*)&qf[ks + 4][r]);  // x2 pair
                float2 c0 = tb[j], c1 = tb[j + 1];
                float y1x = (a.x * c0.x + bb.x * c0.y) * f;
                float y2x = (-a.x * c0.y + bb.x * c0.x) * f;
                float y1y = (a.y * c1.x + bb.y * c1.y) * f;
                float y2y = (-a.y * c1.y + bb.y * c1.x) * f;
                qf[ks][r]     = pack2(y1x, y1y);
                qf[ks + 4][r] = pack2(y2x, y2y);
            }
        }
    }

    float4 of[16];
#pragma unroll
    for (int i = 0; i < 16; i++) of[i] = make_float4(0.f, 0.f, 0.f, 0.f);
    float m0 = -FLT_MAX, m1 = -FLT_MAX, l0 = 0.f, l1 = 0.f;

    for (int kt = 0; kt <= qt; kt++) {
        const int kbase = kt * 64;
        const int ktn = (kt + 1 <= qt) ? kt + 1 : qt;

        cp_wait<1>();            // K[kt] ready (V[kt] pending)
        __syncthreads();

        // S = Q K^T
        float4 s[8];
#pragma unroll
        for (int nt = 0; nt < 8; nt++) s[nt] = make_float4(0.f, 0.f, 0.f, 0.f);
#pragma unroll
        for (int ks = 0; ks < 8; ks++) {
            const uint32_t chunk = (uint32_t)(2 * ks + lb8);
#pragma unroll
            for (int half = 0; half < 2; half++) {
                const int row0 = (2 * half) * 16 + lb16 * 8 + lx;
                const int row1 = (2 * half + 1) * 16 + lb16 * 8 + lx;
                uint32_t kb0[4], kb1[4];
                ldsm_x4(kb0, sKu + (uint32_t)(row0 * 256) + (swz(chunk, row0) << 4));
                ldsm_x4(kb1, sKu + (uint32_t)(row1 * 256) + (swz(chunk, row1) << 4));
                mma_f16(s[4*half],     qf[ks], kb0[0], kb0[1]);
                mma_f16(s[4*half + 1], qf[ks], kb0[2], kb0[3]);
                mma_f16(s[4*half + 2], qf[ks], kb1[0], kb1[1]);
                mma_f16(s[4*half + 3], qf[ks], kb1[2], kb1[3]);
            }
        }
        __syncthreads();         // everyone done reading Ks
        ld_K(ktn);               // prefetch next K (overlaps softmax + PV)

        // causal mask on diagonal tile
        if (kt == qt) {
            int r0 = qb + wid * 16 + gid;
#pragma unroll
            for (int nt = 0; nt < 8; nt++) {
                int c = kbase + nt * 8 + 2 * tig;
                if (c > r0)         s[nt].x = -FLT_MAX;
                if (c + 1 > r0)     s[nt].y = -FLT_MAX;
                if (c > r0 + 8)     s[nt].z = -FLT_MAX;
                if (c + 1 > r0 + 8) s[nt].w = -FLT_MAX;
            }
        }

        // online softmax, base 2
        float mt0 = -FLT_MAX, mt1 = -FLT_MAX;
#pragma unroll
        for (int nt = 0; nt < 8; nt++) {
            mt0 = fmaxf(mt0, fmaxf(s[nt].x, s[nt].y));
            mt1 = fmaxf(mt1, fmaxf(s[nt].z, s[nt].w));
        }
        mt0 = fmaxf(mt0, __shfl_xor_sync(0xffffffffu, mt0, 1));
        mt0 = fmaxf(mt0, __shfl_xor_sync(0xffffffffu, mt0, 2));
        mt1 = fmaxf(mt1, __shfl_xor_sync(0xffffffffu, mt1, 1));
        mt1 = fmaxf(mt1, __shfl_xor_sync(0xffffffffu, mt1, 2));

        float mn0 = fmaxf(m0, mt0), mn1 = fmaxf(m1, mt1);
        float a0 = exp2f(m0 - mn0), a1 = exp2f(m1 - mn1);
        float sum0 = 0.f, sum1 = 0.f;
#pragma unroll
        for (int nt = 0; nt < 8; nt++) {
            s[nt].x = exp2f(s[nt].x - mn0);
            s[nt].y = exp2f(s[nt].y - mn0);
            s[nt].z = exp2f(s[nt].z - mn1);
            s[nt].w = exp2f(s[nt].w - mn1);
            sum0 += s[nt].x + s[nt].y;
            sum1 += s[nt].z + s[nt].w;
        }
        sum0 += __shfl_xor_sync(0xffffffffu, sum0, 1);
        sum0 += __shfl_xor_sync(0xffffffffu, sum0, 2);
        sum1 += __shfl_xor_sync(0xffffffffu, sum1, 1);
        sum1 += __shfl_xor_sync(0xffffffffu, sum1, 2);

        l0 = l0 * a0 + sum0;
        l1 = l1 * a1 + sum1;
        m0 = mn0; m1 = mn1;
#pragma unroll
        for (int dt = 0; dt < 16; dt++) {
            of[dt].x *= a0; of[dt].y *= a0;
            of[dt].z *= a1; of[dt].w *= a1;
        }

        // P: fp32 C-frags -> fp16 A-frags (registers only)
        uint32_t ph[4][4];
#pragma unroll
        for (int kv = 0; kv < 4; kv++) {
            ph[kv][0] = pack2(s[2*kv].x,     s[2*kv].y);
            ph[kv][1] = pack2(s[2*kv].z,     s[2*kv].w);
            ph[kv][2] = pack2(s[2*kv + 1].x, s[2*kv + 1].y);
            ph[kv][3] = pack2(s[2*kv + 1].z, s[2*kv + 1].w);
        }

        cp_wait<1>();            // V[kt] ready (next K pending)
        __syncthreads();

        // O += P V
#pragma unroll
        for (int kv = 0; kv < 4; kv++) {
            const int row = kv * 16 + lb8 * 8 + lx;
            const uint32_t va = sVu + (uint32_t)(row * 256);
#pragma unroll
            for (int nb = 0; nb < 8; nb++) {
                uint32_t vb[4];
                ldsm_x4t(vb, va + (swz((uint32_t)(2 * nb + lb16), row) << 4));
                mma_f16(of[2*nb],     ph[kv], vb[0], vb[1]);
                mma_f16(of[2*nb + 1], ph[kv], vb[2], vb[3]);
            }
        }
        __syncthreads();
        ld_V(ktn);
    }
    cp_wait<0>();

    // epilogue: normalize, convert fp16, store y
    float inv0 = 1.0f / l0, inv1 = 1.0f / l1;
    __half* Yg = g_yh + (size_t)(b * SEQ + qb + wid * 16 + gid) * DIM + h * HD;
#pragma unroll
    for (int dt = 0; dt < 16; dt++) {
        int c = dt * 8 + 2 * tig;
        *(uint32_t*)&Yg[c]           = pack2(of[dt].x * inv0, of[dt].y * inv0);
        *(uint32_t*)&Yg[8 * DIM + c] = pack2(of[dt].z * inv1, of[dt].w * inv1);
    }
}

// ---------------------------------------------------------------------------
extern "C" void kernel_launch(void* const* d_in, const int* in_sizes, int n_in,
                              void* d_out, int out_size)
{
    (void)in_sizes; (void)n_in; (void)out_size;
    const float* x  = (const float*)d_in[0];
    const float* qg = (const float*)d_in[1];
    const float* Wq = (const float*)d_in[2];
    const float* Wk = (const float*)d_in[3];
    const float* Wv = (const float*)d_in[4];
    const float* Wp = (const float*)d_in[5];
    float* out = (float*)d_out;

    __half *qkvh, *xh, *wqkvh, *wph, *yh;
    cudaGetSymbolAddress((void**)&qkvh, g_qkvh);
    cudaGetSymbolAddress((void**)&xh, g_xh);
    cudaGetSymbolAddress((void**)&wqkvh, g_wqkvh);
    cudaGetSymbolAddress((void**)&wph, g_wph);
    cudaGetSymbolAddress((void**)&yh, g_yh);

    // launch 1: fp16 conversion + rope table
    prep_all<<<BLH_X + BLH_WQ + BLH_WK + BLH_WV + BLH_WP + BLH_TB, 256>>>(x, Wq, Wk, Wv, Wp);

    size_t gsm = 3 * (size_t)STAGE_B;  // 98304
    cudaFuncSetAttribute(gemm_h<__half>, cudaFuncAttributeMaxDynamicSharedMemorySize, (int)gsm);
    cudaFuncSetAttribute(gemm_h<float>,  cudaFuncAttributeMaxDynamicSharedMemorySize, (int)gsm);

    // launch 2: fused QKV projection (fp16 in, fp16 out)
    gemm_h<__half><<<dim3(QKVD / 128, BT / 128), 128, gsm>>>(xh, wqkvh, qkvh, QKVD, DIM);

    // launch 3: norm + rope for k heads only (q fused into attention)
    norm_k<<<(BT * 4) / 8, 256>>>();

    // launch 4: flash attention with fused q norm/rope (profiled slot)
    size_t asm_ = 32768;
    cudaFuncSetAttribute(attn3, cudaFuncAttributeMaxDynamicSharedMemorySize, (int)asm_);
    attn3<<<dim3(SEQ / 64, BATCH * NHEADS), 128, asm_>>>(qg);

    // launch 5: output projection (fp16 in, fp32 out)
    gemm_h<float><<<dim3(DIM / 128, BT / 128), 128, gsm>>>(yh, wph, out, DIM, DIM);
}